// round 1
// baseline (speedup 1.0000x reference)
#include <cuda_runtime.h>

// DynamicMaskHead fused kernel:
//   per-instance 3-layer 1x1-conv MLP over [relx, rely, feats(8)] -> logits [128,192]
//   + aligned_bilinear x2 upsample -> out [256, 1, 256, 384] fp32
//
// Strategy: one block = (instance, 16-row tile). Compute 17 logit rows (1 halo
// row above, clamped) into smem, then write the 32 upsampled output rows with
// float4 stores. Math uses packed fma.rn.f32x2 over output-channel pairs so
// the per-instance weights pack once into registers (169 regs) and the packed
// FMA count per pixel is ~78 instead of 152 scalar FFMAs.

#define WW   192
#define HH   128
#define HWSZ (192*128)
#define CIN  8
#define TH   16
#define OWW  384
#define OHH  256
#define NP   169

__device__ __forceinline__ float2 ffma2(float2 a, float2 b, float2 c) {
    float2 d;
    asm("fma.rn.f32x2 %0, %1, %2, %3;"
        : "=l"(reinterpret_cast<unsigned long long&>(d))
        : "l"(reinterpret_cast<unsigned long long&>(a)),
          "l"(reinterpret_cast<unsigned long long&>(b)),
          "l"(reinterpret_cast<unsigned long long&>(c)));
    return d;
}
__device__ __forceinline__ float2 relu2(float2 v) {
    return make_float2(fmaxf(v.x, 0.f), fmaxf(v.y, 0.f));
}
__device__ __forceinline__ float2 splat(float s) { return make_float2(s, s); }

__global__ __launch_bounds__(128) void dyn_mask_head_kernel(
    const float* __restrict__ mask_feats,   // [2, 8, 128, 192]
    const float* __restrict__ params,       // [n_inst, 169]
    const float* __restrict__ locs,         // [n_inst, 2] (x, y)
    const float* __restrict__ soi,          // [5]
    const int*   __restrict__ im_inds,      // [n_inst]
    const int*   __restrict__ fpn_levels,   // [n_inst]
    float*       __restrict__ out)          // [n_inst, 1, 256, 384]
{
    const int n   = blockIdx.y;
    const int r0  = blockIdx.x * TH;
    const int tid = threadIdx.x;

    __shared__ float sP[NP];
    __shared__ __align__(16) float sL[TH + 1][WW];

    for (int j = tid; j < NP; j += 128) sP[j] = params[n * NP + j];
    __syncthreads();

    // ---- pack per-instance weights into registers (channel pairs) ----
    float2 w0p[4][10], w1p[4][8], w2p[4], b0p[4], b1p[4];
#pragma unroll
    for (int cp = 0; cp < 4; cp++) {
#pragma unroll
        for (int j = 0; j < 10; j++)
            w0p[cp][j] = make_float2(sP[(2*cp)*10 + j], sP[(2*cp+1)*10 + j]);
#pragma unroll
        for (int k = 0; k < 8; k++)
            w1p[cp][k] = make_float2(sP[80 + (2*cp)*8 + k], sP[80 + (2*cp+1)*8 + k]);
        w2p[cp] = make_float2(sP[144 + 2*cp], sP[144 + 2*cp + 1]);
        b0p[cp] = make_float2(sP[152 + 2*cp], sP[152 + 2*cp + 1]);
        b1p[cp] = make_float2(sP[160 + 2*cp], sP[160 + 2*cp + 1]);
    }
    const float b2 = sP[168];

    const int   im  = im_inds[n];
    const float inv = 1.0f / soi[fpn_levels[n]];
    const float lx  = locs[2*n + 0];
    const float ly  = locs[2*n + 1];
    const float* fb = mask_feats + (size_t)im * (CIN * HWSZ);

    // ---- phase 1: logits for rows [r0-1, r0+TH) (halo row clamped) ----
    const int NPIX = (TH + 1) * WW;
    for (int i = tid; i < NPIX; i += 128) {
        const int rl = i / WW;
        const int x  = i - rl * WW;
        const int rc = max(r0 - 1 + rl, 0);
        const float* fp = fb + rc * WW + x;

        float2 fs[8];
#pragma unroll
        for (int k = 0; k < 8; k++) fs[k] = splat(__ldg(fp + k * HWSZ));

        const float2 rxs = splat((lx - (float)(x * 8 + 4)) * inv);
        const float2 rys = splat((ly - (float)(rc * 8 + 4)) * inv);

        // layer 0: 10 -> 8, relu (channel-pair packed)
        float2 h0[4];
#pragma unroll
        for (int cp = 0; cp < 4; cp++) {
            float2 a = b0p[cp];
            a = ffma2(w0p[cp][0], rxs, a);
            a = ffma2(w0p[cp][1], rys, a);
#pragma unroll
            for (int k = 0; k < 8; k++) a = ffma2(w0p[cp][2 + k], fs[k], a);
            h0[cp] = relu2(a);
        }
        // splat h0 channels for layer 1 operands
        float2 hs[8];
#pragma unroll
        for (int cp = 0; cp < 4; cp++) {
            hs[2*cp + 0] = splat(h0[cp].x);
            hs[2*cp + 1] = splat(h0[cp].y);
        }
        // layer 1: 8 -> 8, relu
        float2 h1[4];
#pragma unroll
        for (int cp = 0; cp < 4; cp++) {
            float2 a = b1p[cp];
#pragma unroll
            for (int k = 0; k < 8; k++) a = ffma2(w1p[cp][k], hs[k], a);
            h1[cp] = relu2(a);
        }
        // layer 2: 8 -> 1 (pair the reduction over k; no splats needed)
        float2 o2 = make_float2(b2, 0.f);
#pragma unroll
        for (int cp = 0; cp < 4; cp++) o2 = ffma2(w2p[cp], h1[cp], o2);

        sL[rl][x] = o2.x + o2.y;
    }
    __syncthreads();

    // ---- phase 2: aligned_bilinear x2 from smem tile, float4 stores ----
    // out[o] = interp[max(o-1,0)]; interp[j] even -> t[j/2],
    //                               odd  -> 0.5*(t[j>>1] + t[(j>>1)+1])
    float* ob = out + (size_t)n * (OHH * OWW) + (size_t)(2 * r0) * OWW;
    const int NG = 32 * (WW / 2);  // 32 output rows x 96 groups of 4 cols
    for (int i = tid; i < NG; i += 128) {
        const int oyl = i / 96;
        const int m   = i - oyl * 96;
        const int oy  = 2 * r0 + oyl;
        const int iy  = max(oy - 1, 0);
        const int ra  = (iy >> 1) - r0 + 1;   // smem slot of row (iy>>1)

        const int c0 = max(2 * m - 1, 0);
        const int c1 = 2 * m;
        const int c2 = 2 * m + 1;

        float va, vb, vc;
        if (iy & 1) {
            va = 0.5f * (sL[ra][c0] + sL[ra + 1][c0]);
            vb = 0.5f * (sL[ra][c1] + sL[ra + 1][c1]);
            vc = 0.5f * (sL[ra][c2] + sL[ra + 1][c2]);
        } else {
            va = sL[ra][c0];
            vb = sL[ra][c1];
            vc = sL[ra][c2];
        }
        float4 o;
        o.x = 0.5f * (va + vb);   // even ox (left-edge clamp folds in: va==vb at m==0)
        o.y = vb;                 // odd ox
        o.z = 0.5f * (vb + vc);
        o.w = vc;
        *reinterpret_cast<float4*>(ob + oyl * OWW + 4 * m) = o;
    }
}

extern "C" void kernel_launch(void* const* d_in, const int* in_sizes, int n_in,
                              void* d_out, int out_size) {
    const float* mask_feats = (const float*)d_in[0];
    const float* params     = (const float*)d_in[1];
    const float* locs       = (const float*)d_in[2];
    const float* soi        = (const float*)d_in[3];
    const int*   im_inds    = (const int*)d_in[4];
    const int*   fpn_levels = (const int*)d_in[5];
    float*       out        = (float*)d_out;

    const int n_inst = in_sizes[4];          // im_inds count = 256
    dim3 grid(HH / TH, n_inst);
    dyn_mask_head_kernel<<<grid, 128>>>(mask_feats, params, locs, soi,
                                        im_inds, fpn_levels, out);
}

// round 2
// speedup vs baseline: 1.0885x; 1.0885x over previous
#include <cuda_runtime.h>

// DynamicMaskHead fused kernel, round 2:
//  - 2 pixels (adjacent columns) per thread per iteration -> LDG.64 feat loads
//  - double-buffered feat prefetch to cover L2 latency
//  - packed fma.rn.f32x2 over output-channel pairs, weights register-resident
//  - fused aligned_bilinear x2 from smem logit tile

#define WW    192
#define HH    128
#define HWSZ  (192*128)
#define CIN   8
#define TH    16
#define NROWS (TH + 1)            // halo row above
#define NUNIT (NROWS * (WW/2))    // 17 * 96 = 1632 column-pair units
#define OWW   384
#define OHH   256
#define NP    169

__device__ __forceinline__ float2 ffma2(float2 a, float2 b, float2 c) {
    float2 d;
    asm("fma.rn.f32x2 %0, %1, %2, %3;"
        : "=l"(reinterpret_cast<unsigned long long&>(d))
        : "l"(reinterpret_cast<unsigned long long&>(a)),
          "l"(reinterpret_cast<unsigned long long&>(b)),
          "l"(reinterpret_cast<unsigned long long&>(c)));
    return d;
}
__device__ __forceinline__ float2 relu2(float2 v) {
    return make_float2(fmaxf(v.x, 0.f), fmaxf(v.y, 0.f));
}
__device__ __forceinline__ float2 splat(float s) { return make_float2(s, s); }

__global__ __launch_bounds__(128) void dyn_mask_head_kernel(
    const float* __restrict__ mask_feats,   // [2, 8, 128, 192]
    const float* __restrict__ params,       // [n_inst, 169]
    const float* __restrict__ locs,         // [n_inst, 2] (x, y)
    const float* __restrict__ soi,          // [5]
    const int*   __restrict__ im_inds,      // [n_inst]
    const int*   __restrict__ fpn_levels,   // [n_inst]
    float*       __restrict__ out)          // [n_inst, 1, 256, 384]
{
    const int n   = blockIdx.y;
    const int r0  = blockIdx.x * TH;
    const int tid = threadIdx.x;

    __shared__ float sP[NP];
    __shared__ __align__(16) float sL[NROWS][WW];

    for (int j = tid; j < NP; j += 128) sP[j] = params[n * NP + j];
    __syncthreads();

    // ---- pack per-instance weights into registers (channel pairs) ----
    float2 w0p[4][10], w1p[4][8], w2p[4], b0p[4], b1p[4];
#pragma unroll
    for (int cp = 0; cp < 4; cp++) {
#pragma unroll
        for (int j = 0; j < 10; j++)
            w0p[cp][j] = make_float2(sP[(2*cp)*10 + j], sP[(2*cp+1)*10 + j]);
#pragma unroll
        for (int k = 0; k < 8; k++)
            w1p[cp][k] = make_float2(sP[80 + (2*cp)*8 + k], sP[80 + (2*cp+1)*8 + k]);
        w2p[cp] = make_float2(sP[144 + 2*cp], sP[144 + 2*cp + 1]);
        b0p[cp] = make_float2(sP[152 + 2*cp], sP[152 + 2*cp + 1]);
        b1p[cp] = make_float2(sP[160 + 2*cp], sP[160 + 2*cp + 1]);
    }
    const float b2 = sP[168];

    const int   im  = im_inds[n];
    const float inv = 1.0f / soi[fpn_levels[n]];
    const float lx  = locs[2*n + 0];
    const float ly  = locs[2*n + 1];
    const float* fb = mask_feats + (size_t)im * (CIN * HWSZ);

    // ---- phase 1: logits for rows [r0-1, r0+TH), 2 px/thread/iter ----
    // unit i -> rl = i/96 (local row), m = i%96 (column pair), cols 2m, 2m+1
    int i = tid;
    float2 fcur[8];
    {
        const int rl = i / 96, m = i - rl * 96;
        const int rc = max(r0 - 1 + rl, 0);
        const float* fp = fb + rc * WW + 2 * m;
#pragma unroll
        for (int k = 0; k < 8; k++)
            fcur[k] = *reinterpret_cast<const float2*>(fp + k * HWSZ);
    }

    const int NITER = (NUNIT + 127) / 128;   // 13
#pragma unroll 1
    for (int it = 0; it < NITER; it++) {
        const int rl = i / 96, m = i - rl * 96;
        const int rc = max(r0 - 1 + rl, 0);

        // prefetch next unit's feats
        const int inext = i + 128;
        float2 fnext[8];
        if (inext < NUNIT) {
            const int rl2 = inext / 96, m2 = inext - rl2 * 96;
            const int rc2 = max(r0 - 1 + rl2, 0);
            const float* fp2 = fb + rc2 * WW + 2 * m2;
#pragma unroll
            for (int k = 0; k < 8; k++)
                fnext[k] = *reinterpret_cast<const float2*>(fp2 + k * HWSZ);
        }

        if (i < NUNIT) {
            const float2 rys  = splat((ly - (float)(rc * 8 + 4)) * inv);
            const float  rx0  = (lx - (float)(16 * m + 4)) * inv;
            const float2 rx0s = splat(rx0);
            const float2 rx1s = splat(rx0 - 8.0f * inv);

            // layer 0: both pixels, 8 independent f2 accumulators
            float2 a0[4], a1[4];
#pragma unroll
            for (int cp = 0; cp < 4; cp++) {
                a0[cp] = ffma2(w0p[cp][0], rx0s, b0p[cp]);
                a1[cp] = ffma2(w0p[cp][0], rx1s, b0p[cp]);
                a0[cp] = ffma2(w0p[cp][1], rys, a0[cp]);
                a1[cp] = ffma2(w0p[cp][1], rys, a1[cp]);
            }
#pragma unroll
            for (int k = 0; k < 8; k++) {
                const float2 f0s = splat(fcur[k].x);
                const float2 f1s = splat(fcur[k].y);
#pragma unroll
                for (int cp = 0; cp < 4; cp++) {
                    a0[cp] = ffma2(w0p[cp][2 + k], f0s, a0[cp]);
                    a1[cp] = ffma2(w0p[cp][2 + k], f1s, a1[cp]);
                }
            }

            // relu + splat hidden channels
            float2 h0s[8], h1s[8];
#pragma unroll
            for (int cp = 0; cp < 4; cp++) {
                const float2 r0v = relu2(a0[cp]);
                const float2 r1v = relu2(a1[cp]);
                h0s[2*cp + 0] = splat(r0v.x);
                h0s[2*cp + 1] = splat(r0v.y);
                h1s[2*cp + 0] = splat(r1v.x);
                h1s[2*cp + 1] = splat(r1v.y);
            }

            // layer 1: both pixels
            float2 c0[4], c1[4];
#pragma unroll
            for (int cp = 0; cp < 4; cp++) { c0[cp] = b1p[cp]; c1[cp] = b1p[cp]; }
#pragma unroll
            for (int k = 0; k < 8; k++) {
#pragma unroll
                for (int cp = 0; cp < 4; cp++) {
                    c0[cp] = ffma2(w1p[cp][k], h0s[k], c0[cp]);
                    c1[cp] = ffma2(w1p[cp][k], h1s[k], c1[cp]);
                }
            }

            // layer 2: pair the k-reduction
            float2 o0 = make_float2(b2, 0.f), o1 = make_float2(b2, 0.f);
#pragma unroll
            for (int cp = 0; cp < 4; cp++) {
                o0 = ffma2(w2p[cp], relu2(c0[cp]), o0);
                o1 = ffma2(w2p[cp], relu2(c1[cp]), o1);
            }

            *reinterpret_cast<float2*>(&sL[rl][2 * m]) =
                make_float2(o0.x + o0.y, o1.x + o1.y);
        }

#pragma unroll
        for (int k = 0; k < 8; k++) fcur[k] = fnext[k];
        i = inext;
    }
    __syncthreads();

    // ---- phase 2: aligned_bilinear x2 from smem tile, float4 stores ----
    // out[o] = interp[max(o-1,0)]; interp[j] even -> t[j/2],
    //                               odd  -> 0.5*(t[j>>1] + t[(j>>1)+1])
    float* ob = out + (size_t)n * (OHH * OWW) + (size_t)(2 * r0) * OWW;
    const int NG = 32 * (WW / 2);  // 32 output rows x 96 groups of 4 cols
    for (int g = tid; g < NG; g += 128) {
        const int oyl = g / 96;
        const int m   = g - oyl * 96;
        const int oy  = 2 * r0 + oyl;
        const int iy  = max(oy - 1, 0);
        const int ra  = (iy >> 1) - r0 + 1;   // smem slot of row (iy>>1)

        const int cA = max(2 * m - 1, 0);
        const int cB = 2 * m;
        const int cC = 2 * m + 1;

        float va, vb, vc;
        if (iy & 1) {
            va = 0.5f * (sL[ra][cA] + sL[ra + 1][cA]);
            vb = 0.5f * (sL[ra][cB] + sL[ra + 1][cB]);
            vc = 0.5f * (sL[ra][cC] + sL[ra + 1][cC]);
        } else {
            va = sL[ra][cA];
            vb = sL[ra][cB];
            vc = sL[ra][cC];
        }
        float4 o;
        o.x = 0.5f * (va + vb);   // even ox (left-edge clamp folds in at m==0)
        o.y = vb;                 // odd ox
        o.z = 0.5f * (vb + vc);
        o.w = vc;
        *reinterpret_cast<float4*>(ob + oyl * OWW + 4 * m) = o;
    }
}

extern "C" void kernel_launch(void* const* d_in, const int* in_sizes, int n_in,
                              void* d_out, int out_size) {
    const float* mask_feats = (const float*)d_in[0];
    const float* params     = (const float*)d_in[1];
    const float* locs       = (const float*)d_in[2];
    const float* soi        = (const float*)d_in[3];
    const int*   im_inds    = (const int*)d_in[4];
    const int*   fpn_levels = (const int*)d_in[5];
    float*       out        = (float*)d_out;

    const int n_inst = in_sizes[4];          // 256
    dim3 grid(HH / TH, n_inst);
    dyn_mask_head_kernel<<<grid, 128>>>(mask_feats, params, locs, soi,
                                        im_inds, fpn_levels, out);
}

// round 3
// speedup vs baseline: 1.4784x; 1.3581x over previous
#include <cuda_runtime.h>

// DynamicMaskHead fused kernel, round 3:
//  - f32x2 lanes packed over adjacent PIXELS (not channels): no per-pixel splats
//  - per-instance weights stored DUPLICATED in smem -> LDS.128 yields two
//    weight splats per load, 16B-aligned padded layout
//  - 4 pixels per thread per iteration, LDG.128 feat loads
//  - low register footprint -> __launch_bounds__(128,4): 4 blocks/SM
//  - fused aligned_bilinear x2 from smem logit tile

#define WW    192
#define HH    128
#define HWSZ  (192*128)
#define CIN   8
#define TH    16
#define NROWS (TH + 1)           // halo row above
#define UPR   (WW/4)             // 48 four-pixel units per row
#define NUNIT (NROWS * UPR)      // 816
#define OWW   384
#define OHH   256
#define NP    169

__device__ __forceinline__ float2 ffma2(float2 a, float2 b, float2 c) {
    float2 d;
    asm("fma.rn.f32x2 %0, %1, %2, %3;"
        : "=l"(reinterpret_cast<unsigned long long&>(d))
        : "l"(reinterpret_cast<unsigned long long&>(a)),
          "l"(reinterpret_cast<unsigned long long&>(b)),
          "l"(reinterpret_cast<unsigned long long&>(c)));
    return d;
}
__device__ __forceinline__ float2 relu2(float2 v) {
    return make_float2(fmaxf(v.x, 0.f), fmaxf(v.y, 0.f));
}
__device__ __forceinline__ float2 f2(float a, float b) { return make_float2(a, b); }

__global__ __launch_bounds__(128, 4) void dyn_mask_head_kernel(
    const float* __restrict__ mask_feats,   // [2, 8, 128, 192]
    const float* __restrict__ params,       // [n_inst, 169]
    const float* __restrict__ locs,         // [n_inst, 2] (x, y)
    const float* __restrict__ soi,          // [5]
    const int*   __restrict__ im_inds,      // [n_inst]
    const int*   __restrict__ fpn_levels,   // [n_inst]
    float*       __restrict__ out)          // [n_inst, 1, 256, 384]
{
    const int n   = blockIdx.y;
    const int r0  = blockIdx.x * TH;
    const int tid = threadIdx.x;

    // duplicated weights: every scalar stored twice -> LDS gives ready splats
    __shared__ __align__(16) float sw0[8][12]; // [c]: w(j=0..9) dup (10*2=..wait 2j,2j+1), last pair = bias dup
    __shared__ __align__(16) float sw1[8][20]; // [c]: 8 weights dup (16) + bias dup (2) + pad
    __shared__ __align__(16) float sw2[20];    // 8 weights dup + bias dup + pad
    __shared__ __align__(16) float sL[NROWS][WW];

    // stage + duplicate params
    {
        const float* p = params + n * NP;
        for (int t = tid; t < NP; t += 128) {
            float v = __ldg(p + t);
            if (t < 80) {
                int c = t / 10, j = t - 10 * c;
                if (j < 5) { sw0[c][2*j] = v; sw0[c][2*j+1] = v; }
                else { /* j in 5..9 stored beyond: need 10 dup slots but row is 12 */ }
            }
            // handled fully below
        }
    }
    // NOTE: sw0 row holds only 12 floats; 10 duplicated weights need 20.
    // Redo with correct sizes (kept above decl unused halves? no) —
    __syncthreads();

    // ---- correct staging (see layout) ----
    // layout: sw0b[c][24]: w0..w9 dup (20) + bias dup (2) + pad(2)
    __shared__ __align__(16) float sw0b[8][24];
    {
        const float* p = params + n * NP;
        for (int t = tid; t < NP; t += 128) {
            float v = __ldg(p + t);
            if (t < 80) {
                int c = t / 10, j = t - 10 * c;
                sw0b[c][2*j] = v; sw0b[c][2*j+1] = v;
            } else if (t < 144) {
                int q = t - 80; int c = q >> 3, j = q & 7;
                sw1[c][2*j] = v; sw1[c][2*j+1] = v;
            } else if (t < 152) {
                int j = t - 144;
                sw2[2*j] = v; sw2[2*j+1] = v;
            } else if (t < 160) {
                int c = t - 152;
                sw0b[c][20] = v; sw0b[c][21] = v;
            } else if (t < 168) {
                int c = t - 160;
                sw1[c][16] = v; sw1[c][17] = v;
            } else {
                sw2[16] = v; sw2[17] = v;
            }
        }
    }
    __syncthreads();

    const int   im  = im_inds[n];
    const float inv = 1.0f / soi[fpn_levels[n]];
    const float lx  = locs[2*n + 0];
    const float ly  = locs[2*n + 1];
    const float* fb = mask_feats + (size_t)im * (CIN * HWSZ);

    // ---- phase 1: logits, 4 consecutive pixels per thread per iter ----
#pragma unroll 1
    for (int it = 0; it < 7; it++) {
        const int i = tid + it * 128;
        if (i >= NUNIT) break;
        const int rl = i / UPR;
        const int m  = i - rl * UPR;
        const int x0 = 4 * m;
        const int rc = max(r0 - 1 + rl, 0);

        const float* fp = fb + rc * WW + x0;
        float4 f[8];
#pragma unroll
        for (int k = 0; k < 8; k++)
            f[k] = *reinterpret_cast<const float4*>(fp + k * HWSZ);

        const float ryv = (ly - (float)(rc * 8 + 4)) * inv;
        const float2 ryd = f2(ryv, ryv);
        const float rxv = (lx - (float)(x0 * 8 + 4)) * inv;
        const float s8  = 8.0f * inv;
        const float2 rxA = f2(rxv, rxv - s8);
        const float2 rxB = f2(rxv - 2.f * s8, rxv - 3.f * s8);

        // layer 0: 10 -> 8, relu.  A = pixels 0,1  B = pixels 2,3
        float2 hA[8], hB[8];
#pragma unroll
        for (int c = 0; c < 8; c++) {
            const float4* wc = reinterpret_cast<const float4*>(sw0b[c]);
            const float2 bd = *reinterpret_cast<const float2*>(&sw0b[c][20]);
            float4 w01 = wc[0];
            float2 aA = ffma2(f2(w01.x, w01.y), rxA, bd);
            float2 aB = ffma2(f2(w01.x, w01.y), rxB, bd);
            aA = ffma2(f2(w01.z, w01.w), ryd, aA);
            aB = ffma2(f2(w01.z, w01.w), ryd, aB);
#pragma unroll
            for (int kk = 0; kk < 4; kk++) {     // feats k = 2kk, 2kk+1
                float4 wp = wc[1 + kk];
                aA = ffma2(f2(wp.x, wp.y), f2(f[2*kk].x,   f[2*kk].y),   aA);
                aB = ffma2(f2(wp.x, wp.y), f2(f[2*kk].z,   f[2*kk].w),   aB);
                aA = ffma2(f2(wp.z, wp.w), f2(f[2*kk+1].x, f[2*kk+1].y), aA);
                aB = ffma2(f2(wp.z, wp.w), f2(f[2*kk+1].z, f[2*kk+1].w), aB);
            }
            hA[c] = relu2(aA);
            hB[c] = relu2(aB);
        }

        // layer 1: 8 -> 8, relu
        float2 gA[8], gB[8];
#pragma unroll
        for (int c = 0; c < 8; c++) {
            const float4* wc = reinterpret_cast<const float4*>(sw1[c]);
            const float2 bd = *reinterpret_cast<const float2*>(&sw1[c][16]);
            float2 aA = bd, aB = bd;
#pragma unroll
            for (int kk = 0; kk < 4; kk++) {     // in-ch k = 2kk, 2kk+1
                float4 wp = wc[kk];
                aA = ffma2(f2(wp.x, wp.y), hA[2*kk],   aA);
                aB = ffma2(f2(wp.x, wp.y), hB[2*kk],   aB);
                aA = ffma2(f2(wp.z, wp.w), hA[2*kk+1], aA);
                aB = ffma2(f2(wp.z, wp.w), hB[2*kk+1], aB);
            }
            gA[c] = relu2(aA);
            gB[c] = relu2(aB);
        }

        // layer 2: 8 -> 1
        {
            const float4* wc = reinterpret_cast<const float4*>(sw2);
            const float2 bd = *reinterpret_cast<const float2*>(&sw2[16]);
            float2 oA = bd, oB = bd;
#pragma unroll
            for (int kk = 0; kk < 4; kk++) {
                float4 wp = wc[kk];
                oA = ffma2(f2(wp.x, wp.y), gA[2*kk],   oA);
                oB = ffma2(f2(wp.x, wp.y), gB[2*kk],   oB);
                oA = ffma2(f2(wp.z, wp.w), gA[2*kk+1], oA);
                oB = ffma2(f2(wp.z, wp.w), gB[2*kk+1], oB);
            }
            float4 v = make_float4(oA.x, oA.y, oB.x, oB.y);
            *reinterpret_cast<float4*>(&sL[rl][x0]) = v;
        }
    }
    __syncthreads();

    // ---- phase 2: aligned_bilinear x2 from smem tile, float4 stores ----
    // out[o] = interp[max(o-1,0)]; interp[j] even -> t[j/2],
    //                               odd  -> 0.5*(t[j>>1] + t[(j>>1)+1])
    float* ob = out + (size_t)n * (OHH * OWW) + (size_t)(2 * r0) * OWW;
    const int NG = 32 * (WW / 2);  // 32 output rows x 96 groups of 4 cols
    for (int g = tid; g < NG; g += 128) {
        const int oyl = g / 96;
        const int m   = g - oyl * 96;
        const int oy  = 2 * r0 + oyl;
        const int iy  = max(oy - 1, 0);
        const int ra  = (iy >> 1) - r0 + 1;   // smem slot of row (iy>>1)

        const int cA = max(2 * m - 1, 0);
        const int cB = 2 * m;
        const int cC = 2 * m + 1;

        float va, vb, vc;
        if (iy & 1) {
            va = 0.5f * (sL[ra][cA] + sL[ra + 1][cA]);
            vb = 0.5f * (sL[ra][cB] + sL[ra + 1][cB]);
            vc = 0.5f * (sL[ra][cC] + sL[ra + 1][cC]);
        } else {
            va = sL[ra][cA];
            vb = sL[ra][cB];
            vc = sL[ra][cC];
        }
        float4 o;
        o.x = 0.5f * (va + vb);   // even ox (left-edge clamp folds in at m==0)
        o.y = vb;                 // odd ox
        o.z = 0.5f * (vb + vc);
        o.w = vc;
        *reinterpret_cast<float4*>(ob + oyl * OWW + 4 * m) = o;
    }
}

extern "C" void kernel_launch(void* const* d_in, const int* in_sizes, int n_in,
                              void* d_out, int out_size) {
    const float* mask_feats = (const float*)d_in[0];
    const float* params     = (const float*)d_in[1];
    const float* locs       = (const float*)d_in[2];
    const float* soi        = (const float*)d_in[3];
    const int*   im_inds    = (const int*)d_in[4];
    const int*   fpn_levels = (const int*)d_in[5];
    float*       out        = (float*)d_out;

    const int n_inst = in_sizes[4];          // 256
    dim3 grid(HH / TH, n_inst);
    dyn_mask_head_kernel<<<grid, 128>>>(mask_feats, params, locs, soi,
                                        im_inds, fpn_levels, out);
}